// round 6
// baseline (speedup 1.0000x reference)
#include <cuda_runtime.h>
#include <cstdint>

#define S_   64
#define W_   128
#define D_   256
#define HW_  256
#define G3W_ 768
#define HS_  512
#define G3S_ 1536
#define C_   13

// ---------------- scratch (device globals; no allocation allowed) ----------
__device__ float g_X [2097152];    // [w][s][d]           128*64*256
__device__ float g_GI[12582912];   // [d][w][s][768]      2*128*64*768
__device__ float g_H [4194304];    // [d][w][s][256]
__device__ float g_ssum[S_*HS_];         // [s][512]
__device__ float g_GIS[2*S_*G3S_];       // [d][s][1536]
__device__ float g_SE[S_*1024];          // [s][1024]
__device__ float g_US[S_*1024];          // [s][1024]

// ---------------- helpers --------------------------------------------------
__device__ __forceinline__ unsigned su32(const void* p) {
    return (unsigned)__cvta_generic_to_shared(p);
}
// single-MUFU tanh (sm_75+), abs err ~1e-4 — output tolerance is 1e-3
__device__ __forceinline__ float ftanh(float x) {
    float y;
    asm("tanh.approx.f32 %0, %1;" : "=f"(y) : "f"(x));
    return y;
}
// sigmoid(x) = 0.5*tanh(x/2) + 0.5  (1 MUFU + 2 FMA)
__device__ __forceinline__ float fsigm(float x) {
    return fmaf(ftanh(0.5f * x), 0.5f, 0.5f);
}

// ---------------- 1. embedding gather --------------------------------------
__global__ void k_gather(const int* __restrict__ doc, const float* __restrict__ emb) {
    int q  = blockIdx.x * blockDim.x + threadIdx.x;   // over 524288 float4s
    int d4 = q & 63;
    int rs = q >> 6;            // = w*64 + s
    int s  = rs & 63, w = rs >> 6;
    int tok = doc[s * W_ + w];
    ((float4*)g_X)[q] = ((const float4*)emb)[(long)tok * 64 + d4];
}

// ---------------- 2a. fast 128x128x8 SGEMM: C = A @ B^T + bias -------------
__global__ __launch_bounds__(256, 2) void k_gemm128(
    const float* __restrict__ A, const float* __restrict__ B,
    const float* __restrict__ bias, float* __restrict__ C,
    int M, int N, int K,
    long sAz, long sBz, long sbz, long sCz)
{
    __shared__ float As[2][1056];   // [8][132] x 2
    __shared__ float Bs[2][1056];
    int t  = threadIdx.x;
    int z  = blockIdx.z;
    const float* Ab = A + z * sAz + (long)blockIdx.x * 128 * K;
    const float* Bb = B + z * sBz + (long)blockIdx.y * 128 * K;
    int r  = t >> 1;            // 0..127
    int kc = (t & 1) * 4;       // 0 or 4
    int tx = t & 15, ty = t >> 4;

    float4 av = *(const float4*)&Ab[(long)r * K + kc];
    float4 bv = *(const float4*)&Bb[(long)r * K + kc];
    As[0][(kc+0)*132+r] = av.x; As[0][(kc+1)*132+r] = av.y;
    As[0][(kc+2)*132+r] = av.z; As[0][(kc+3)*132+r] = av.w;
    Bs[0][(kc+0)*132+r] = bv.x; Bs[0][(kc+1)*132+r] = bv.y;
    Bs[0][(kc+2)*132+r] = bv.z; Bs[0][(kc+3)*132+r] = bv.w;
    __syncthreads();

    float acc[8][8] = {};
    int nb = K >> 3;
    for (int kb = 0; kb < nb; kb++) {
        if (kb + 1 < nb) {
            av = *(const float4*)&Ab[(long)r * K + (kb + 1) * 8 + kc];
            bv = *(const float4*)&Bb[(long)r * K + (kb + 1) * 8 + kc];
        }
        const float* Ac = As[kb & 1];
        const float* Bc = Bs[kb & 1];
#pragma unroll
        for (int k = 0; k < 8; k++) {
            float4 a0 = *(const float4*)&Ac[k*132 + ty*4];
            float4 a1 = *(const float4*)&Ac[k*132 + 64 + ty*4];
            float4 b0 = *(const float4*)&Bc[k*132 + tx*4];
            float4 b1 = *(const float4*)&Bc[k*132 + 64 + tx*4];
            float a[8] = {a0.x,a0.y,a0.z,a0.w,a1.x,a1.y,a1.z,a1.w};
            float b[8] = {b0.x,b0.y,b0.z,b0.w,b1.x,b1.y,b1.z,b1.w};
#pragma unroll
            for (int i = 0; i < 8; i++)
#pragma unroll
                for (int j = 0; j < 8; j++)
                    acc[i][j] = fmaf(a[i], b[j], acc[i][j]);
        }
        if (kb + 1 < nb) {
            int nx = (kb + 1) & 1;
            As[nx][(kc+0)*132+r] = av.x; As[nx][(kc+1)*132+r] = av.y;
            As[nx][(kc+2)*132+r] = av.z; As[nx][(kc+3)*132+r] = av.w;
            Bs[nx][(kc+0)*132+r] = bv.x; Bs[nx][(kc+1)*132+r] = bv.y;
            Bs[nx][(kc+2)*132+r] = bv.z; Bs[nx][(kc+3)*132+r] = bv.w;
        }
        __syncthreads();
    }

    const float* bp = bias + z * sbz + blockIdx.y * 128;
    float4 bq0 = *(const float4*)&bp[tx*4];
    float4 bq1 = *(const float4*)&bp[64 + tx*4];
#pragma unroll
    for (int i = 0; i < 8; i++) {
        int m = blockIdx.x * 128 + ((i < 4) ? ty*4 + i : 64 + ty*4 + (i-4));
        long base = z * sCz + (long)m * N + blockIdx.y * 128;
        float4 o0, o1;
        o0.x = acc[i][0]+bq0.x; o0.y = acc[i][1]+bq0.y;
        o0.z = acc[i][2]+bq0.z; o0.w = acc[i][3]+bq0.w;
        o1.x = acc[i][4]+bq1.x; o1.y = acc[i][5]+bq1.y;
        o1.z = acc[i][6]+bq1.z; o1.w = acc[i][7]+bq1.w;
        *(float4*)&C[base + tx*4]      = o0;
        *(float4*)&C[base + 64 + tx*4] = o1;
    }
}

// ---------------- 2b. fused word attention + sum over words ----------------
__global__ __launch_bounds__(256, 2) void k_uword(
    const float* __restrict__ waW, const float* __restrict__ wab)
{
    __shared__ float As[2][1056];
    __shared__ float Bs[2][1056];
    int t  = threadIdx.x;
    int s  = blockIdx.x;                 // sentence
    const float* Bb = waW + (long)blockIdx.y * 128 * HS_;
    int r  = t >> 1;                     // 0..127 (= word index for A)
    int kc = (t & 1) * 4;
    int tx = t & 15, ty = t >> 4;

    auto loadA = [&](int k0) -> float4 {
        int k   = k0 + kc;
        int dir = k >> 8;
        int hw  = k & 255;
        return *(const float4*)&g_H[((long)(dir * W_ + r) * S_ + s) * HW_ + hw];
    };

    float4 av = loadA(0);
    float4 bv = *(const float4*)&Bb[(long)r * HS_ + kc];
    As[0][(kc+0)*132+r] = av.x; As[0][(kc+1)*132+r] = av.y;
    As[0][(kc+2)*132+r] = av.z; As[0][(kc+3)*132+r] = av.w;
    Bs[0][(kc+0)*132+r] = bv.x; Bs[0][(kc+1)*132+r] = bv.y;
    Bs[0][(kc+2)*132+r] = bv.z; Bs[0][(kc+3)*132+r] = bv.w;
    __syncthreads();

    float acc[8][8] = {};
    const int nb = HS_ >> 3;   // 64
    for (int kb = 0; kb < nb; kb++) {
        if (kb + 1 < nb) {
            av = loadA((kb + 1) * 8);
            bv = *(const float4*)&Bb[(long)r * HS_ + (kb + 1) * 8 + kc];
        }
        const float* Ac = As[kb & 1];
        const float* Bc = Bs[kb & 1];
#pragma unroll
        for (int k = 0; k < 8; k++) {
            float4 a0 = *(const float4*)&Ac[k*132 + ty*4];
            float4 a1 = *(const float4*)&Ac[k*132 + 64 + ty*4];
            float4 b0 = *(const float4*)&Bc[k*132 + tx*4];
            float4 b1 = *(const float4*)&Bc[k*132 + 64 + tx*4];
            float a[8] = {a0.x,a0.y,a0.z,a0.w,a1.x,a1.y,a1.z,a1.w};
            float b[8] = {b0.x,b0.y,b0.z,b0.w,b1.x,b1.y,b1.z,b1.w};
#pragma unroll
            for (int i = 0; i < 8; i++)
#pragma unroll
                for (int j = 0; j < 8; j++)
                    acc[i][j] = fmaf(a[i], b[j], acc[i][j]);
        }
        if (kb + 1 < nb) {
            int nx = (kb + 1) & 1;
            As[nx][(kc+0)*132+r] = av.x; As[nx][(kc+1)*132+r] = av.y;
            As[nx][(kc+2)*132+r] = av.z; As[nx][(kc+3)*132+r] = av.w;
            Bs[nx][(kc+0)*132+r] = bv.x; Bs[nx][(kc+1)*132+r] = bv.y;
            Bs[nx][(kc+2)*132+r] = bv.z; Bs[nx][(kc+3)*132+r] = bv.w;
        }
        __syncthreads();
    }

    const float* bp = wab + blockIdx.y * 128;
    float rsum[8];
#pragma unroll
    for (int j = 0; j < 8; j++) {
        int col = (j < 4) ? tx*4 + j : 64 + tx*4 + (j-4);
        float bj = bp[col];
        float sum = 0.f;
#pragma unroll
        for (int i = 0; i < 8; i++) sum += ftanh(acc[i][j] + bj);
        rsum[j] = sum;
    }
    __syncthreads();
    float* red = &As[0][0];               // [16][132]
#pragma unroll
    for (int j = 0; j < 8; j++) {
        int col = (j < 4) ? tx*4 + j : 64 + tx*4 + (j-4);
        red[ty*132 + col] = rsum[j];
    }
    __syncthreads();
    if (t < 128) {
        float a = 0.f;
#pragma unroll
        for (int y = 0; y < 16; y++) a += red[y*132 + t];
        g_ssum[s * HS_ + blockIdx.y * 128 + t] = a;
    }
}

// ---------------- 2c. small generic GEMM (M=64 cases) ----------------------
#define BM 64
#define BN 64
#define BK 32
__global__ __launch_bounds__(256) void k_gemm(
    const float* __restrict__ A, const float* __restrict__ B,
    const float* __restrict__ bias, float* __restrict__ C,
    int M, int N, int K, int actTanh,
    long sAz, long sBz, long sbz, long sCz)
{
    __shared__ float As2[BK][BM + 1];
    __shared__ float Bs2[BK][BN + 1];
    int t  = threadIdx.x;
    int tx = t & 15, ty = t >> 4;
    int z  = blockIdx.z;
    const float* Ab = A + z * sAz + (long)blockIdx.x * BM * K;
    const float* Bb = B + z * sBz + (long)blockIdx.y * BN * K;
    float acc[4][4] = {};
    for (int k0 = 0; k0 < K; k0 += BK) {
#pragma unroll
        for (int j = 0; j < 8; j++) {
            int idx = j * 256 + t;
            int m = idx >> 5, k = idx & 31;
            As2[k][m] = Ab[(long)m * K + k0 + k];
            Bs2[k][m] = Bb[(long)m * K + k0 + k];
        }
        __syncthreads();
#pragma unroll 8
        for (int k = 0; k < BK; k++) {
            float a0 = As2[k][ty*4+0], a1 = As2[k][ty*4+1], a2 = As2[k][ty*4+2], a3 = As2[k][ty*4+3];
            float b0 = Bs2[k][tx*4+0], b1 = Bs2[k][tx*4+1], b2 = Bs2[k][tx*4+2], b3 = Bs2[k][tx*4+3];
            acc[0][0]=fmaf(a0,b0,acc[0][0]); acc[0][1]=fmaf(a0,b1,acc[0][1]);
            acc[0][2]=fmaf(a0,b2,acc[0][2]); acc[0][3]=fmaf(a0,b3,acc[0][3]);
            acc[1][0]=fmaf(a1,b0,acc[1][0]); acc[1][1]=fmaf(a1,b1,acc[1][1]);
            acc[1][2]=fmaf(a1,b2,acc[1][2]); acc[1][3]=fmaf(a1,b3,acc[1][3]);
            acc[2][0]=fmaf(a2,b0,acc[2][0]); acc[2][1]=fmaf(a2,b1,acc[2][1]);
            acc[2][2]=fmaf(a2,b2,acc[2][2]); acc[2][3]=fmaf(a2,b3,acc[2][3]);
            acc[3][0]=fmaf(a3,b0,acc[3][0]); acc[3][1]=fmaf(a3,b1,acc[3][1]);
            acc[3][2]=fmaf(a3,b2,acc[3][2]); acc[3][3]=fmaf(a3,b3,acc[3][3]);
        }
        __syncthreads();
    }
    const float* bp = bias + z * sbz;
#pragma unroll
    for (int i = 0; i < 4; i++) {
        int m = blockIdx.x * BM + ty * 4 + i;
#pragma unroll
        for (int j = 0; j < 4; j++) {
            int n = blockIdx.y * BN + tx * 4 + j;
            float v = acc[i][j] + bp[n];
            if (actTanh) v = ftanh(v);
            C[z * sCz + (long)m * N + n] = v;
        }
    }
}

// ---------------- 3. word GRU recurrence (cluster of 4, 256 thr) -----------
// grid.x = 128: rank = blockIdx&3 owns h dims [rank*64, rank*64+64).
// 256 threads: squad = tid>>6 (sentence s0+squad), jj = tid&63 (dim).
// 2 warps per SMSP -> cross-warp latency hiding (the round-4 version had 1).
#define PADK 260                                    // conflict-free LDS.128
#define GRU_SMEM ((3*64*PADK + 2*4*256 + 192) * 4)  // 208640 B

extern __shared__ float smem_gru[];

__global__ void __cluster_dims__(4, 1, 1) __launch_bounds__(256, 1)
k_wordgru(const float* __restrict__ wWh, const float* __restrict__ wbh)
{
    float* Wsh  = smem_gru;                 // [3*64][PADK]
    float* hbuf = Wsh + 3 * 64 * PADK;      // [2][4][256]
    float* bhs  = hbuf + 2 * 4 * 256;       // [192]

    int rank = blockIdx.x & 3;
    int cid  = blockIdx.x >> 2;
    int d    = cid >> 4;
    int s0   = (cid & 15) * 4;
    int j0   = rank * 64;
    int tid  = threadIdx.x;

    const float4* w4g = (const float4*)wWh;
    for (int i = tid; i < 3 * 64 * 64; i += 256) {
        int g  = i >> 12;
        int r2 = i & 4095;
        int jj = r2 >> 6, k4 = r2 & 63;
        float4 v = w4g[((long)d * G3W_ + g * 256 + j0 + jj) * 64 + k4];
        *(float4*)&Wsh[(g * 64 + jj) * PADK + k4 * 4] = v;
    }
    for (int i = tid; i < 192; i += 256)
        bhs[i] = wbh[d * G3W_ + (i >> 6) * 256 + j0 + (i & 63)];
    for (int i = tid; i < 4 * 256; i += 256) hbuf[i] = 0.f;
    __syncthreads();
    asm volatile("barrier.cluster.arrive.aligned;" ::: "memory");
    asm volatile("barrier.cluster.wait.aligned;"   ::: "memory");

    int squad = tid >> 6;          // 0..3 -> sentence
    int jj    = tid & 63;
    int dim   = j0 + jj;
    int s     = s0 + squad;
    float bhr = bhs[jj], bhz = bhs[64 + jj], bhn = bhs[128 + jj];
    const float4* wR = (const float4*)&Wsh[( 0 + jj) * PADK];
    const float4* wZ = (const float4*)&Wsh[( 64 + jj) * PADK];
    const float4* wN = (const float4*)&Wsh[(128 + jj) * PADK];

    // hoist DSMEM target addresses (constant per buffer parity)
    unsigned rem[2][4];
#pragma unroll
    for (int b = 0; b < 2; b++) {
        unsigned la = su32(&hbuf[(b * 4 + squad) * 256 + dim]);
#pragma unroll
        for (int tcta = 0; tcta < 4; tcta++)
            asm volatile("mapa.shared::cluster.u32 %0, %1, %2;"
                         : "=r"(rem[b][tcta]) : "r"(la), "r"(tcta));
    }

    const long strideW = (long)S_ * G3W_;
    const float* gi = g_GI + ((long)(d * W_) * S_ + s) * G3W_ + dim;
    float* gh = g_H + ((long)(d * W_) * S_ + s) * HW_ + dim;

    // prefetch step 0
    float pR = __ldg(gi), pZ = __ldg(gi + 256), pN = __ldg(gi + 512);

    for (int w = 0; w < W_; w++) {
        int cur = w & 1, nxt = cur ^ 1;

        float giR = pR, giZ = pZ, giN = pN;
        const float* gnx = (w + 1 < W_) ? gi + strideW : gi;   // clamp, harmless
        pR = __ldg(gnx); pZ = __ldg(gnx + 256); pN = __ldg(gnx + 512);

        const float4* h4 = (const float4*)&hbuf[(cur * 4 + squad) * 256];
        float aR = 0, aZ = 0, aN = 0;
#pragma unroll 8
        for (int k4 = 0; k4 < 64; k4++) {
            float4 wr = wR[k4], wz = wZ[k4], wn = wN[k4];
            float4 hv = h4[k4];
            aR = fmaf(wr.x, hv.x, aR); aR = fmaf(wr.y, hv.y, aR);
            aR = fmaf(wr.z, hv.z, aR); aR = fmaf(wr.w, hv.w, aR);
            aZ = fmaf(wz.x, hv.x, aZ); aZ = fmaf(wz.y, hv.y, aZ);
            aZ = fmaf(wz.z, hv.z, aZ); aZ = fmaf(wz.w, hv.w, aZ);
            aN = fmaf(wn.x, hv.x, aN); aN = fmaf(wn.y, hv.y, aN);
            aN = fmaf(wn.z, hv.z, aN); aN = fmaf(wn.w, hv.w, aN);
        }
        float hold = hbuf[(cur * 4 + squad) * 256 + dim];
        float r  = fsigm(giR + aR + bhr);
        float z  = fsigm(giZ + aZ + bhz);
        float n  = ftanh(giN + r * (aN + bhn));
        float hp = (1.f - z) * n + z * hold;

        // push h to all 4 CTAs, release, overlap global store with barrier
#pragma unroll
        for (int tcta = 0; tcta < 4; tcta++)
            asm volatile("st.shared::cluster.f32 [%0], %1;"
                         :: "r"(rem[nxt][tcta]), "f"(hp) : "memory");
        asm volatile("barrier.cluster.arrive.aligned;" ::: "memory");  // release

        *gh = hp;
        gh += (long)S_ * HW_;
        gi += strideW;

        asm volatile("barrier.cluster.wait.aligned;"   ::: "memory");  // acquire
    }
}

// ---------------- 6. sentence encoder pointwise (h0 = 0) -------------------
__global__ void k_sentenc(const float* __restrict__ sbh) {
    int idx = blockIdx.x * blockDim.x + threadIdx.x;  // 65536
    int d = idx >> 15;
    int s = (idx >> 9) & 63;
    int h = idx & 511;
    const float* gi = &g_GIS[(d * S_ + s) * G3S_];
    float r  = fsigm(gi[h]       + sbh[d * G3S_ + h]);
    float zz = fsigm(gi[512 + h] + sbh[d * G3S_ + 512 + h]);
    float n  = ftanh(gi[1024 + h] + r * sbh[d * G3S_ + 1024 + h]);
    g_SE[s * 1024 + d * 512 + h] = (1.f - zz) * n;
}

// ---------------- 7. outputs -----------------------------------------------
__global__ void k_ones(float* out, int n) {
    int i = blockIdx.x * 256 + threadIdx.x;
    if (i < n) out[i] = 1.0f;
}

__global__ void k_final(const float* __restrict__ doW, const float* __restrict__ dob,
                        float* __restrict__ out, int out_size) {
    __shared__ float doc[1024];
    __shared__ float red[256];
    __shared__ float logit[16];
    int t = threadIdx.x;
    for (int n = t; n < 1024; n += 256) {
        float a = 0.f;
        for (int s = 0; s < S_; s++) a += g_US[s * 1024 + n];
        doc[n] = a;
    }
    __syncthreads();
    for (int c = 0; c < C_; c++) {
        float p = 0.f;
        for (int n = t; n < 1024; n += 256) p = fmaf(doc[n], doW[c * 1024 + n], p);
        red[t] = p; __syncthreads();
        for (int st = 128; st > 0; st >>= 1) {
            if (t < st) red[t] += red[t + st];
            __syncthreads();
        }
        if (t == 0) logit[c] = red[0] + dob[c];
        __syncthreads();
    }
    if (t == 0) {
        float m = -1e30f;
        for (int c = 0; c < C_; c++) m = fmaxf(m, logit[c]);
        float se = 0.f;
        for (int c = 0; c < C_; c++) se += expf(logit[c] - m);   // keep accurate
        float lse = m + logf(se);
        for (int c = 0; c < C_; c++) out[out_size - C_ + c] = logit[c] - lse;
    }
}

// ---------------- launcher -------------------------------------------------
extern "C" void kernel_launch(void* const* d_in, const int* in_sizes, int n_in,
                              void* d_out, int out_size) {
    const int*   doc = (const int*)  d_in[0];
    const float* emb = (const float*)d_in[1];
    const float* wWi = (const float*)d_in[2];
    const float* wWh = (const float*)d_in[3];
    const float* wbi = (const float*)d_in[4];
    const float* wbh = (const float*)d_in[5];
    const float* sWi = (const float*)d_in[6];
    const float* sbi = (const float*)d_in[8];
    const float* sbh = (const float*)d_in[9];
    const float* waW = (const float*)d_in[10];
    const float* wab = (const float*)d_in[11];
    const float* saW = (const float*)d_in[13];
    const float* sab = (const float*)d_in[14];
    const float* doW = (const float*)d_in[16];
    const float* dob = (const float*)d_in[17];
    float* out = (float*)d_out;

    cudaFuncSetAttribute(k_wordgru, cudaFuncAttributeMaxDynamicSharedMemorySize, GRU_SMEM);

    float *pX, *pGI, *pS, *pGIS, *pSE, *pUS;
    cudaGetSymbolAddress((void**)&pX,  g_X);
    cudaGetSymbolAddress((void**)&pGI, g_GI);
    cudaGetSymbolAddress((void**)&pS,  g_ssum);
    cudaGetSymbolAddress((void**)&pGIS,g_GIS);
    cudaGetSymbolAddress((void**)&pSE, g_SE);
    cudaGetSymbolAddress((void**)&pUS, g_US);

    // 1. gather embeddings
    k_gather<<<2048, 256>>>(doc, emb);

    // 2. GI[d] = X @ wWi[d].T + wbi[d]   (M=8192, N=768, K=256)
    k_gemm128<<<dim3(64, 6, 2), 256>>>(pX, wWi, wbi, pGI, 8192, 768, 256,
                                       0, 768L * 256, 768, 8192L * 768);

    // 3. recurrence -> g_H  (256 threads: 2 warps/SMSP)
    k_wordgru<<<128, 256, GRU_SMEM>>>(wWh, wbh);

    // 4+5+6 fused: g_ssum[s] = sum_w tanh(wordenc[s,w] @ waW.T + wab)
    k_uword<<<dim3(64, 4), 256>>>(waW, wab);

    // 7. GIS[d] = sent_summ @ sWi[d].T + sbi[d]  (M=64, N=1536, K=512)
    k_gemm<<<dim3(1, 24, 2), 256>>>(pS, sWi, sbi, pGIS, 64, 1536, 512, 0,
                                    0, 1536L * 512, 1536, 64L * 1536);

    // 8. sentenc pointwise
    k_sentenc<<<256, 256>>>(sbh);

    // 9. u_sent = tanh(sentenc @ saW.T + sab)   (M=64, N=1024, K=1024)
    k_gemm<<<dim3(1, 16, 1), 256>>>(pSE, saW, sab, pUS, 64, 1024, 1024, 1, 0, 0, 0, 0);

    // 10. outputs
    int nOnes = out_size - C_;
    k_ones<<<(nOnes + 255) / 256, 256>>>(out, nOnes);
    k_final<<<1, 256>>>(doW, dob, out, out_size);
}

// round 7
// speedup vs baseline: 1.3261x; 1.3261x over previous
#include <cuda_runtime.h>
#include <cstdint>

#define S_   64
#define W_   128
#define D_   256
#define HW_  256
#define G3W_ 768
#define HS_  512
#define G3S_ 1536
#define C_   13

// ---------------- scratch (device globals; no allocation allowed) ----------
__device__ float g_X [2097152];    // [w][s][d]           128*64*256
__device__ float g_GI[12582912];   // [d][w][s][768]      2*128*64*768
__device__ float g_H [4194304];    // [d][w][s][256]
__device__ float g_ssum[S_*HS_];         // [s][512]
__device__ float g_GIS[2*S_*G3S_];       // [d][s][1536]
__device__ float g_SE[S_*1024];          // [s][1024]
__device__ float g_US[S_*1024];          // [s][1024]

// ---------------- helpers --------------------------------------------------
__device__ __forceinline__ unsigned su32(const void* p) {
    return (unsigned)__cvta_generic_to_shared(p);
}
// single-MUFU tanh (sm_75+), abs err ~1e-4 — output tolerance is 1e-3
__device__ __forceinline__ float ftanh(float x) {
    float y;
    asm("tanh.approx.f32 %0, %1;" : "=f"(y) : "f"(x));
    return y;
}
// sigmoid(x) = 0.5*tanh(x/2) + 0.5  (1 MUFU + 2 FMA)
__device__ __forceinline__ float fsigm(float x) {
    return fmaf(ftanh(0.5f * x), 0.5f, 0.5f);
}

// ---------------- 1. embedding gather --------------------------------------
__global__ void k_gather(const int* __restrict__ doc, const float* __restrict__ emb) {
    int q  = blockIdx.x * blockDim.x + threadIdx.x;   // over 524288 float4s
    int d4 = q & 63;
    int rs = q >> 6;            // = w*64 + s
    int s  = rs & 63, w = rs >> 6;
    int tok = doc[s * W_ + w];
    ((float4*)g_X)[q] = ((const float4*)emb)[(long)tok * 64 + d4];
}

// ---------------- 2a. fast 128x128x8 SGEMM: C = A @ B^T + bias -------------
__global__ __launch_bounds__(256, 2) void k_gemm128(
    const float* __restrict__ A, const float* __restrict__ B,
    const float* __restrict__ bias, float* __restrict__ C,
    int M, int N, int K,
    long sAz, long sBz, long sbz, long sCz)
{
    __shared__ float As[2][1056];   // [8][132] x 2
    __shared__ float Bs[2][1056];
    int t  = threadIdx.x;
    int z  = blockIdx.z;
    const float* Ab = A + z * sAz + (long)blockIdx.x * 128 * K;
    const float* Bb = B + z * sBz + (long)blockIdx.y * 128 * K;
    int r  = t >> 1;            // 0..127
    int kc = (t & 1) * 4;       // 0 or 4
    int tx = t & 15, ty = t >> 4;

    float4 av = *(const float4*)&Ab[(long)r * K + kc];
    float4 bv = *(const float4*)&Bb[(long)r * K + kc];
    As[0][(kc+0)*132+r] = av.x; As[0][(kc+1)*132+r] = av.y;
    As[0][(kc+2)*132+r] = av.z; As[0][(kc+3)*132+r] = av.w;
    Bs[0][(kc+0)*132+r] = bv.x; Bs[0][(kc+1)*132+r] = bv.y;
    Bs[0][(kc+2)*132+r] = bv.z; Bs[0][(kc+3)*132+r] = bv.w;
    __syncthreads();

    float acc[8][8] = {};
    int nb = K >> 3;
    for (int kb = 0; kb < nb; kb++) {
        if (kb + 1 < nb) {
            av = *(const float4*)&Ab[(long)r * K + (kb + 1) * 8 + kc];
            bv = *(const float4*)&Bb[(long)r * K + (kb + 1) * 8 + kc];
        }
        const float* Ac = As[kb & 1];
        const float* Bc = Bs[kb & 1];
#pragma unroll
        for (int k = 0; k < 8; k++) {
            float4 a0 = *(const float4*)&Ac[k*132 + ty*4];
            float4 a1 = *(const float4*)&Ac[k*132 + 64 + ty*4];
            float4 b0 = *(const float4*)&Bc[k*132 + tx*4];
            float4 b1 = *(const float4*)&Bc[k*132 + 64 + tx*4];
            float a[8] = {a0.x,a0.y,a0.z,a0.w,a1.x,a1.y,a1.z,a1.w};
            float b[8] = {b0.x,b0.y,b0.z,b0.w,b1.x,b1.y,b1.z,b1.w};
#pragma unroll
            for (int i = 0; i < 8; i++)
#pragma unroll
                for (int j = 0; j < 8; j++)
                    acc[i][j] = fmaf(a[i], b[j], acc[i][j]);
        }
        if (kb + 1 < nb) {
            int nx = (kb + 1) & 1;
            As[nx][(kc+0)*132+r] = av.x; As[nx][(kc+1)*132+r] = av.y;
            As[nx][(kc+2)*132+r] = av.z; As[nx][(kc+3)*132+r] = av.w;
            Bs[nx][(kc+0)*132+r] = bv.x; Bs[nx][(kc+1)*132+r] = bv.y;
            Bs[nx][(kc+2)*132+r] = bv.z; Bs[nx][(kc+3)*132+r] = bv.w;
        }
        __syncthreads();
    }

    const float* bp = bias + z * sbz + blockIdx.y * 128;
    float4 bq0 = *(const float4*)&bp[tx*4];
    float4 bq1 = *(const float4*)&bp[64 + tx*4];
#pragma unroll
    for (int i = 0; i < 8; i++) {
        int m = blockIdx.x * 128 + ((i < 4) ? ty*4 + i : 64 + ty*4 + (i-4));
        long base = z * sCz + (long)m * N + blockIdx.y * 128;
        float4 o0, o1;
        o0.x = acc[i][0]+bq0.x; o0.y = acc[i][1]+bq0.y;
        o0.z = acc[i][2]+bq0.z; o0.w = acc[i][3]+bq0.w;
        o1.x = acc[i][4]+bq1.x; o1.y = acc[i][5]+bq1.y;
        o1.z = acc[i][6]+bq1.z; o1.w = acc[i][7]+bq1.w;
        *(float4*)&C[base + tx*4]      = o0;
        *(float4*)&C[base + 64 + tx*4] = o1;
    }
}

// ---------------- 2b. fused word attention + sum over words ----------------
__global__ __launch_bounds__(256, 2) void k_uword(
    const float* __restrict__ waW, const float* __restrict__ wab)
{
    __shared__ float As[2][1056];
    __shared__ float Bs[2][1056];
    int t  = threadIdx.x;
    int s  = blockIdx.x;                 // sentence
    const float* Bb = waW + (long)blockIdx.y * 128 * HS_;
    int r  = t >> 1;                     // 0..127 (= word index for A)
    int kc = (t & 1) * 4;
    int tx = t & 15, ty = t >> 4;

    auto loadA = [&](int k0) -> float4 {
        int k   = k0 + kc;
        int dir = k >> 8;
        int hw  = k & 255;
        return *(const float4*)&g_H[((long)(dir * W_ + r) * S_ + s) * HW_ + hw];
    };

    float4 av = loadA(0);
    float4 bv = *(const float4*)&Bb[(long)r * HS_ + kc];
    As[0][(kc+0)*132+r] = av.x; As[0][(kc+1)*132+r] = av.y;
    As[0][(kc+2)*132+r] = av.z; As[0][(kc+3)*132+r] = av.w;
    Bs[0][(kc+0)*132+r] = bv.x; Bs[0][(kc+1)*132+r] = bv.y;
    Bs[0][(kc+2)*132+r] = bv.z; Bs[0][(kc+3)*132+r] = bv.w;
    __syncthreads();

    float acc[8][8] = {};
    const int nb = HS_ >> 3;   // 64
    for (int kb = 0; kb < nb; kb++) {
        if (kb + 1 < nb) {
            av = loadA((kb + 1) * 8);
            bv = *(const float4*)&Bb[(long)r * HS_ + (kb + 1) * 8 + kc];
        }
        const float* Ac = As[kb & 1];
        const float* Bc = Bs[kb & 1];
#pragma unroll
        for (int k = 0; k < 8; k++) {
            float4 a0 = *(const float4*)&Ac[k*132 + ty*4];
            float4 a1 = *(const float4*)&Ac[k*132 + 64 + ty*4];
            float4 b0 = *(const float4*)&Bc[k*132 + tx*4];
            float4 b1 = *(const float4*)&Bc[k*132 + 64 + tx*4];
            float a[8] = {a0.x,a0.y,a0.z,a0.w,a1.x,a1.y,a1.z,a1.w};
            float b[8] = {b0.x,b0.y,b0.z,b0.w,b1.x,b1.y,b1.z,b1.w};
#pragma unroll
            for (int i = 0; i < 8; i++)
#pragma unroll
                for (int j = 0; j < 8; j++)
                    acc[i][j] = fmaf(a[i], b[j], acc[i][j]);
        }
        if (kb + 1 < nb) {
            int nx = (kb + 1) & 1;
            As[nx][(kc+0)*132+r] = av.x; As[nx][(kc+1)*132+r] = av.y;
            As[nx][(kc+2)*132+r] = av.z; As[nx][(kc+3)*132+r] = av.w;
            Bs[nx][(kc+0)*132+r] = bv.x; Bs[nx][(kc+1)*132+r] = bv.y;
            Bs[nx][(kc+2)*132+r] = bv.z; Bs[nx][(kc+3)*132+r] = bv.w;
        }
        __syncthreads();
    }

    const float* bp = wab + blockIdx.y * 128;
    float rsum[8];
#pragma unroll
    for (int j = 0; j < 8; j++) {
        int col = (j < 4) ? tx*4 + j : 64 + tx*4 + (j-4);
        float bj = bp[col];
        float sum = 0.f;
#pragma unroll
        for (int i = 0; i < 8; i++) sum += ftanh(acc[i][j] + bj);
        rsum[j] = sum;
    }
    __syncthreads();
    float* red = &As[0][0];               // [16][132]
#pragma unroll
    for (int j = 0; j < 8; j++) {
        int col = (j < 4) ? tx*4 + j : 64 + tx*4 + (j-4);
        red[ty*132 + col] = rsum[j];
    }
    __syncthreads();
    if (t < 128) {
        float a = 0.f;
#pragma unroll
        for (int y = 0; y < 16; y++) a += red[y*132 + t];
        g_ssum[s * HS_ + blockIdx.y * 128 + t] = a;
    }
}

// ---------------- 2c. small generic GEMM (M=64 cases) ----------------------
#define BM 64
#define BN 64
#define BK 32
__global__ __launch_bounds__(256) void k_gemm(
    const float* __restrict__ A, const float* __restrict__ B,
    const float* __restrict__ bias, float* __restrict__ C,
    int M, int N, int K, int actTanh,
    long sAz, long sBz, long sbz, long sCz)
{
    __shared__ float As2[BK][BM + 1];
    __shared__ float Bs2[BK][BN + 1];
    int t  = threadIdx.x;
    int tx = t & 15, ty = t >> 4;
    int z  = blockIdx.z;
    const float* Ab = A + z * sAz + (long)blockIdx.x * BM * K;
    const float* Bb = B + z * sBz + (long)blockIdx.y * BN * K;
    float acc[4][4] = {};
    for (int k0 = 0; k0 < K; k0 += BK) {
#pragma unroll
        for (int j = 0; j < 8; j++) {
            int idx = j * 256 + t;
            int m = idx >> 5, k = idx & 31;
            As2[k][m] = Ab[(long)m * K + k0 + k];
            Bs2[k][m] = Bb[(long)m * K + k0 + k];
        }
        __syncthreads();
#pragma unroll 8
        for (int k = 0; k < BK; k++) {
            float a0 = As2[k][ty*4+0], a1 = As2[k][ty*4+1], a2 = As2[k][ty*4+2], a3 = As2[k][ty*4+3];
            float b0 = Bs2[k][tx*4+0], b1 = Bs2[k][tx*4+1], b2 = Bs2[k][tx*4+2], b3 = Bs2[k][tx*4+3];
            acc[0][0]=fmaf(a0,b0,acc[0][0]); acc[0][1]=fmaf(a0,b1,acc[0][1]);
            acc[0][2]=fmaf(a0,b2,acc[0][2]); acc[0][3]=fmaf(a0,b3,acc[0][3]);
            acc[1][0]=fmaf(a1,b0,acc[1][0]); acc[1][1]=fmaf(a1,b1,acc[1][1]);
            acc[1][2]=fmaf(a1,b2,acc[1][2]); acc[1][3]=fmaf(a1,b3,acc[1][3]);
            acc[2][0]=fmaf(a2,b0,acc[2][0]); acc[2][1]=fmaf(a2,b1,acc[2][1]);
            acc[2][2]=fmaf(a2,b2,acc[2][2]); acc[2][3]=fmaf(a2,b3,acc[2][3]);
            acc[3][0]=fmaf(a3,b0,acc[3][0]); acc[3][1]=fmaf(a3,b1,acc[3][1]);
            acc[3][2]=fmaf(a3,b2,acc[3][2]); acc[3][3]=fmaf(a3,b3,acc[3][3]);
        }
        __syncthreads();
    }
    const float* bp = bias + z * sbz;
#pragma unroll
    for (int i = 0; i < 4; i++) {
        int m = blockIdx.x * BM + ty * 4 + i;
#pragma unroll
        for (int j = 0; j < 4; j++) {
            int n = blockIdx.y * BN + tx * 4 + j;
            float v = acc[i][j] + bp[n];
            if (actTanh) v = ftanh(v);
            C[z * sCz + (long)m * N + n] = v;
        }
    }
}

// ---------------- 3. word GRU recurrence (cluster of 4, K-split) -----------
// 32 clusters x (dir, 4 sentences). Rank owns h dims [rank*64, rank*64+64).
// 256 threads: thread = (jj = warp*8 + lane&7, kq = lane>>3).
// Each thread: ALL 4 sentences over its K-quarter -> every Wh element is
// read from SMEM exactly ONCE per step per CTA (crossbar-minimal).
// Partial sums reduced over kq via shfl.xor(8|16); thread kq finishes
// sentence kq's gates. h rows stored with per-64 skew (stride 72 words)
// so the 4 distinct kq broadcast addresses hit disjoint banks.
#define PADK 260                  // weight row pitch: conflict-free LDS.128
#define HROW 288                  // h row pitch: 4 x 72 (64 data + 8 pad)
#define GRU_SMEM ((3*64*PADK + 2*4*HROW + 192) * 4)   // 209664 B

extern __shared__ float smem_gru[];

__global__ void __cluster_dims__(4, 1, 1) __launch_bounds__(256, 1)
k_wordgru(const float* __restrict__ wWh, const float* __restrict__ wbh)
{
    float* Wsh  = smem_gru;                 // [3*64][PADK]
    float* hbuf = Wsh + 3 * 64 * PADK;      // [2][4][HROW]
    float* bhs  = hbuf + 2 * 4 * HROW;      // [192]

    int rank = blockIdx.x & 3;
    int cid  = blockIdx.x >> 2;
    int d    = cid >> 4;
    int s0   = (cid & 15) * 4;
    int j0   = rank * 64;
    int tid  = threadIdx.x;

    const float4* w4g = (const float4*)wWh;
    for (int i = tid; i < 3 * 64 * 64; i += 256) {
        int g  = i >> 12;
        int r2 = i & 4095;
        int jr = r2 >> 6, k4 = r2 & 63;
        float4 v = w4g[((long)d * G3W_ + g * 256 + j0 + jr) * 64 + k4];
        *(float4*)&Wsh[(g * 64 + jr) * PADK + k4 * 4] = v;
    }
    for (int i = tid; i < 192; i += 256)
        bhs[i] = wbh[d * G3W_ + (i >> 6) * 256 + j0 + (i & 63)];
    for (int i = tid; i < 2 * 4 * HROW; i += 256) hbuf[i] = 0.f;
    __syncthreads();
    asm volatile("barrier.cluster.arrive.aligned;" ::: "memory");
    asm volatile("barrier.cluster.wait.aligned;"   ::: "memory");

    int lane = tid & 31;
    int warp = tid >> 5;            // 0..7
    int jl   = lane & 7;
    int kq   = lane >> 3;           // 0..3 K-quarter; also output sentence
    int jj   = warp * 8 + jl;       // 0..63
    int dim  = j0 + jj;
    int s    = s0 + kq;

    float bhr = bhs[jj], bhz = bhs[64 + jj], bhn = bhs[128 + jj];
    const float4* wR = (const float4*)&Wsh[(  0 + jj) * PADK] + kq * 16;
    const float4* wZ = (const float4*)&Wsh[( 64 + jj) * PADK] + kq * 16;
    const float4* wN = (const float4*)&Wsh[(128 + jj) * PADK] + kq * 16;

    // DSMEM push targets (per buffer parity): skewed h slot for (sent=kq, dim)
    unsigned rem[2][4];
#pragma unroll
    for (int b = 0; b < 2; b++) {
        unsigned la = su32(&hbuf[(b * 4 + kq) * HROW + dim + rank * 8]);
#pragma unroll
        for (int tcta = 0; tcta < 4; tcta++)
            asm volatile("mapa.shared::cluster.u32 %0, %1, %2;"
                         : "=r"(rem[b][tcta]) : "r"(la), "r"(tcta));
    }

    const long strideW = (long)S_ * G3W_;
    const float* gi = g_GI + ((long)(d * W_) * S_ + s) * G3W_ + dim;
    float* gh = g_H + ((long)(d * W_) * S_ + s) * HW_ + dim;

    float pR = __ldg(gi), pZ = __ldg(gi + 256), pN = __ldg(gi + 512);

    for (int w = 0; w < W_; w++) {
        int cur = w & 1, nxt = cur ^ 1;

        float giR = pR, giZ = pZ, giN = pN;
        const float* gnx = (w + 1 < W_) ? gi + strideW : gi;
        pR = __ldg(gnx); pZ = __ldg(gnx + 256); pN = __ldg(gnx + 512);

        const float4* h0 = (const float4*)&hbuf[(cur * 4 + 0) * HROW] + kq * 18;
        const float4* h1 = (const float4*)&hbuf[(cur * 4 + 1) * HROW] + kq * 18;
        const float4* h2 = (const float4*)&hbuf[(cur * 4 + 2) * HROW] + kq * 18;
        const float4* h3 = (const float4*)&hbuf[(cur * 4 + 3) * HROW] + kq * 18;

        float aR0=0,aZ0=0,aN0=0, aR1=0,aZ1=0,aN1=0;
        float aR2=0,aZ2=0,aN2=0, aR3=0,aZ3=0,aN3=0;
#pragma unroll
        for (int i = 0; i < 16; i++) {
            float4 wr = wR[i], wz = wZ[i], wn = wN[i];
            float4 hv;
            hv = h0[i];
            aR0=fmaf(wr.x,hv.x,aR0); aR0=fmaf(wr.y,hv.y,aR0); aR0=fmaf(wr.z,hv.z,aR0); aR0=fmaf(wr.w,hv.w,aR0);
            aZ0=fmaf(wz.x,hv.x,aZ0); aZ0=fmaf(wz.y,hv.y,aZ0); aZ0=fmaf(wz.z,hv.z,aZ0); aZ0=fmaf(wz.w,hv.w,aZ0);
            aN0=fmaf(wn.x,hv.x,aN0); aN0=fmaf(wn.y,hv.y,aN0); aN0=fmaf(wn.z,hv.z,aN0); aN0=fmaf(wn.w,hv.w,aN0);
            hv = h1[i];
            aR1=fmaf(wr.x,hv.x,aR1); aR1=fmaf(wr.y,hv.y,aR1); aR1=fmaf(wr.z,hv.z,aR1); aR1=fmaf(wr.w,hv.w,aR1);
            aZ1=fmaf(wz.x,hv.x,aZ1); aZ1=fmaf(wz.y,hv.y,aZ1); aZ1=fmaf(wz.z,hv.z,aZ1); aZ1=fmaf(wz.w,hv.w,aZ1);
            aN1=fmaf(wn.x,hv.x,aN1); aN1=fmaf(wn.y,hv.y,aN1); aN1=fmaf(wn.z,hv.z,aN1); aN1=fmaf(wn.w,hv.w,aN1);
            hv = h2[i];
            aR2=fmaf(wr.x,hv.x,aR2); aR2=fmaf(wr.y,hv.y,aR2); aR2=fmaf(wr.z,hv.z,aR2); aR2=fmaf(wr.w,hv.w,aR2);
            aZ2=fmaf(wz.x,hv.x,aZ2); aZ2=fmaf(wz.y,hv.y,aZ2); aZ2=fmaf(wz.z,hv.z,aZ2); aZ2=fmaf(wz.w,hv.w,aZ2);
            aN2=fmaf(wn.x,hv.x,aN2); aN2=fmaf(wn.y,hv.y,aN2); aN2=fmaf(wn.z,hv.z,aN2); aN2=fmaf(wn.w,hv.w,aN2);
            hv = h3[i];
            aR3=fmaf(wr.x,hv.x,aR3); aR3=fmaf(wr.y,hv.y,aR3); aR3=fmaf(wr.z,hv.z,aR3); aR3=fmaf(wr.w,hv.w,aR3);
            aZ3=fmaf(wz.x,hv.x,aZ3); aZ3=fmaf(wz.y,hv.y,aZ3); aZ3=fmaf(wz.z,hv.z,aZ3); aZ3=fmaf(wz.w,hv.w,aZ3);
            aN3=fmaf(wn.x,hv.x,aN3); aN3=fmaf(wn.y,hv.y,aN3); aN3=fmaf(wn.z,hv.z,aN3); aN3=fmaf(wn.w,hv.w,aN3);
        }

        // reduce partial sums over kq (lanes ^8, ^16 share jj)
#pragma unroll
        for (int m = 8; m <= 16; m <<= 1) {
            aR0 += __shfl_xor_sync(0xffffffffu, aR0, m);
            aZ0 += __shfl_xor_sync(0xffffffffu, aZ0, m);
            aN0 += __shfl_xor_sync(0xffffffffu, aN0, m);
            aR1 += __shfl_xor_sync(0xffffffffu, aR1, m);
            aZ1 += __shfl_xor_sync(0xffffffffu, aZ1, m);
            aN1 += __shfl_xor_sync(0xffffffffu, aN1, m);
            aR2 += __shfl_xor_sync(0xffffffffu, aR2, m);
            aZ2 += __shfl_xor_sync(0xffffffffu, aZ2, m);
            aN2 += __shfl_xor_sync(0xffffffffu, aN2, m);
            aR3 += __shfl_xor_sync(0xffffffffu, aR3, m);
            aZ3 += __shfl_xor_sync(0xffffffffu, aZ3, m);
            aN3 += __shfl_xor_sync(0xffffffffu, aN3, m);
        }

        // thread kq finishes sentence kq
        float aR = (kq < 2) ? (kq == 0 ? aR0 : aR1) : (kq == 2 ? aR2 : aR3);
        float aZ = (kq < 2) ? (kq == 0 ? aZ0 : aZ1) : (kq == 2 ? aZ2 : aZ3);
        float aN = (kq < 2) ? (kq == 0 ? aN0 : aN1) : (kq == 2 ? aN2 : aN3);

        float hold = hbuf[(cur * 4 + kq) * HROW + dim + rank * 8];
        float r  = fsigm(giR + aR + bhr);
        float z  = fsigm(giZ + aZ + bhz);
        float n  = ftanh(giN + r * (aN + bhn));
        float hp = (1.f - z) * n + z * hold;

        // push h' to all 4 CTAs, release, overlap global store with barrier
#pragma unroll
        for (int tcta = 0; tcta < 4; tcta++)
            asm volatile("st.shared::cluster.f32 [%0], %1;"
                         :: "r"(rem[nxt][tcta]), "f"(hp) : "memory");
        asm volatile("barrier.cluster.arrive.aligned;" ::: "memory");  // release

        *gh = hp;
        gh += (long)S_ * HW_;
        gi += strideW;

        asm volatile("barrier.cluster.wait.aligned;"   ::: "memory");  // acquire
    }
}

// ---------------- 6. sentence encoder pointwise (h0 = 0) -------------------
__global__ void k_sentenc(const float* __restrict__ sbh) {
    int idx = blockIdx.x * blockDim.x + threadIdx.x;  // 65536
    int d = idx >> 15;
    int s = (idx >> 9) & 63;
    int h = idx & 511;
    const float* gi = &g_GIS[(d * S_ + s) * G3S_];
    float r  = fsigm(gi[h]       + sbh[d * G3S_ + h]);
    float zz = fsigm(gi[512 + h] + sbh[d * G3S_ + 512 + h]);
    float n  = ftanh(gi[1024 + h] + r * sbh[d * G3S_ + 1024 + h]);
    g_SE[s * 1024 + d * 512 + h] = (1.f - zz) * n;
}

// ---------------- 7. outputs -----------------------------------------------
__global__ void k_ones(float* out, int n) {
    int i = blockIdx.x * 256 + threadIdx.x;
    if (i < n) out[i] = 1.0f;
}

__global__ void k_final(const float* __restrict__ doW, const float* __restrict__ dob,
                        float* __restrict__ out, int out_size) {
    __shared__ float doc[1024];
    __shared__ float red[256];
    __shared__ float logit[16];
    int t = threadIdx.x;
    for (int n = t; n < 1024; n += 256) {
        float a = 0.f;
        for (int s = 0; s < S_; s++) a += g_US[s * 1024 + n];
        doc[n] = a;
    }
    __syncthreads();
    for (int c = 0; c < C_; c++) {
        float p = 0.f;
        for (int n = t; n < 1024; n += 256) p = fmaf(doc[n], doW[c * 1024 + n], p);
        red[t] = p; __syncthreads();
        for (int st = 128; st > 0; st >>= 1) {
            if (t < st) red[t] += red[t + st];
            __syncthreads();
        }
        if (t == 0) logit[c] = red[0] + dob[c];
        __syncthreads();
    }
    if (t == 0) {
        float m = -1e30f;
        for (int c = 0; c < C_; c++) m = fmaxf(m, logit[c]);
        float se = 0.f;
        for (int c = 0; c < C_; c++) se += expf(logit[c] - m);   // keep accurate
        float lse = m + logf(se);
        for (int c = 0; c < C_; c++) out[out_size - C_ + c] = logit[c] - lse;
    }
}

// ---------------- launcher -------------------------------------------------
extern "C" void kernel_launch(void* const* d_in, const int* in_sizes, int n_in,
                              void* d_out, int out_size) {
    const int*   doc = (const int*)  d_in[0];
    const float* emb = (const float*)d_in[1];
    const float* wWi = (const float*)d_in[2];
    const float* wWh = (const float*)d_in[3];
    const float* wbi = (const float*)d_in[4];
    const float* wbh = (const float*)d_in[5];
    const float* sWi = (const float*)d_in[6];
    const float* sbi = (const float*)d_in[8];
    const float* sbh = (const float*)d_in[9];
    const float* waW = (const float*)d_in[10];
    const float* wab = (const float*)d_in[11];
    const float* saW = (const float*)d_in[13];
    const float* sab = (const float*)d_in[14];
    const float* doW = (const float*)d_in[16];
    const float* dob = (const float*)d_in[17];
    float* out = (float*)d_out;

    cudaFuncSetAttribute(k_wordgru, cudaFuncAttributeMaxDynamicSharedMemorySize, GRU_SMEM);

    float *pX, *pGI, *pS, *pGIS, *pSE, *pUS;
    cudaGetSymbolAddress((void**)&pX,  g_X);
    cudaGetSymbolAddress((void**)&pGI, g_GI);
    cudaGetSymbolAddress((void**)&pS,  g_ssum);
    cudaGetSymbolAddress((void**)&pGIS,g_GIS);
    cudaGetSymbolAddress((void**)&pSE, g_SE);
    cudaGetSymbolAddress((void**)&pUS, g_US);

    // 1. gather embeddings
    k_gather<<<2048, 256>>>(doc, emb);

    // 2. GI[d] = X @ wWi[d].T + wbi[d]   (M=8192, N=768, K=256)
    k_gemm128<<<dim3(64, 6, 2), 256>>>(pX, wWi, wbi, pGI, 8192, 768, 256,
                                       0, 768L * 256, 768, 8192L * 768);

    // 3. recurrence -> g_H  (K-split, weights read once per step)
    k_wordgru<<<128, 256, GRU_SMEM>>>(wWh, wbh);

    // 4+5+6 fused: g_ssum[s] = sum_w tanh(wordenc[s,w] @ waW.T + wab)
    k_uword<<<dim3(64, 4), 256>>>(waW, wab);

    // 7. GIS[d] = sent_summ @ sWi[d].T + sbi[d]  (M=64, N=1536, K=512)
    k_gemm<<<dim3(1, 24, 2), 256>>>(pS, sWi, sbi, pGIS, 64, 1536, 512, 0,
                                    0, 1536L * 512, 1536, 64L * 1536);

    // 8. sentenc pointwise
    k_sentenc<<<256, 256>>>(sbh);

    // 9. u_sent = tanh(sentenc @ saW.T + sab)   (M=64, N=1024, K=1024)
    k_gemm<<<dim3(1, 16, 1), 256>>>(pSE, saW, sab, pUS, 64, 1024, 1024, 1, 0, 0, 0, 0);

    // 10. outputs
    int nOnes = out_size - C_;
    k_ones<<<(nOnes + 255) / 256, 256>>>(out, nOnes);
    k_final<<<1, 256>>>(doW, dob, out, out_size);
}

// round 9
// speedup vs baseline: 1.3350x; 1.0067x over previous
#include <cuda_runtime.h>
#include <cstdint>

#define S_   64
#define W_   128
#define D_   256
#define HW_  256
#define G3W_ 768
#define HS_  512
#define G3S_ 1536
#define C_   13

// ---------------- scratch (device globals; no allocation allowed) ----------
__device__ float g_X [2097152];    // [w][s][d]           128*64*256
__device__ float g_GI[12582912];   // [d][w][s][768]      2*128*64*768
__device__ float g_H [4194304];    // [d][w][s][256]
__device__ float g_ssum[S_*HS_];         // [s][512]
__device__ float g_GIS[2*S_*G3S_];       // [d][s][1536]
__device__ float g_SE[S_*1024];          // [s][1024]
__device__ float g_US[S_*1024];          // [s][1024]

// ---------------- helpers --------------------------------------------------
__device__ __forceinline__ unsigned su32(const void* p) {
    return (unsigned)__cvta_generic_to_shared(p);
}
// single-MUFU tanh (sm_75+), abs err ~1e-4 — output tolerance is 1e-3
__device__ __forceinline__ float ftanh(float x) {
    float y;
    asm("tanh.approx.f32 %0, %1;" : "=f"(y) : "f"(x));
    return y;
}
// sigmoid(x) = 0.5*tanh(x/2) + 0.5  (1 MUFU + 2 FMA)
__device__ __forceinline__ float fsigm(float x) {
    return fmaf(ftanh(0.5f * x), 0.5f, 0.5f);
}
// ---- packed f32x2 (sm_100+, PTX ISA 8.6): two FMAs per instruction --------
__device__ __forceinline__ void ffma2(unsigned long long& d,
                                      unsigned long long a,
                                      unsigned long long b) {
    asm("fma.rn.f32x2 %0, %1, %2, %0;" : "+l"(d) : "l"(a), "l"(b));
}
__device__ __forceinline__ unsigned long long fpack(float x, float y) {
    unsigned long long r;
    asm("mov.b64 %0, {%1, %2};" : "=l"(r) : "f"(x), "f"(y));
    return r;
}
__device__ __forceinline__ float f2lo(unsigned long long d) {
    return __uint_as_float((unsigned)d);
}
__device__ __forceinline__ float f2hi(unsigned long long d) {
    return __uint_as_float((unsigned)(d >> 32));
}
__device__ __forceinline__ float f2sum(unsigned long long d) {
    return f2lo(d) + f2hi(d);
}

// ---------------- 1. embedding gather --------------------------------------
__global__ void k_gather(const int* __restrict__ doc, const float* __restrict__ emb) {
    int q  = blockIdx.x * blockDim.x + threadIdx.x;   // over 524288 float4s
    int d4 = q & 63;
    int rs = q >> 6;            // = w*64 + s
    int s  = rs & 63, w = rs >> 6;
    int tok = doc[s * W_ + w];
    ((float4*)g_X)[q] = ((const float4*)emb)[(long)tok * 64 + d4];
}

// ---------------- 2a. fast 128x128x8 SGEMM (FFMA2): C = A @ B^T + bias -----
__global__ __launch_bounds__(256, 2) void k_gemm128(
    const float* __restrict__ A, const float* __restrict__ B,
    const float* __restrict__ bias, float* __restrict__ C,
    int M, int N, int K,
    long sAz, long sBz, long sbz, long sCz)
{
    __shared__ float As[2][1056];   // [8][132] x 2
    __shared__ float Bs[2][1056];
    int t  = threadIdx.x;
    int z  = blockIdx.z;
    const float* Ab = A + z * sAz + (long)blockIdx.x * 128 * K;
    const float* Bb = B + z * sBz + (long)blockIdx.y * 128 * K;
    int r  = t >> 1;            // 0..127
    int kc = (t & 1) * 4;       // 0 or 4
    int tx = t & 15, ty = t >> 4;

    float4 av = *(const float4*)&Ab[(long)r * K + kc];
    float4 bv = *(const float4*)&Bb[(long)r * K + kc];
    As[0][(kc+0)*132+r] = av.x; As[0][(kc+1)*132+r] = av.y;
    As[0][(kc+2)*132+r] = av.z; As[0][(kc+3)*132+r] = av.w;
    Bs[0][(kc+0)*132+r] = bv.x; Bs[0][(kc+1)*132+r] = bv.y;
    Bs[0][(kc+2)*132+r] = bv.z; Bs[0][(kc+3)*132+r] = bv.w;
    __syncthreads();

    unsigned long long acc2[8][4];
#pragma unroll
    for (int i = 0; i < 8; i++)
#pragma unroll
        for (int j = 0; j < 4; j++) acc2[i][j] = 0ULL;

    int nb = K >> 3;
    for (int kb = 0; kb < nb; kb++) {
        if (kb + 1 < nb) {
            av = *(const float4*)&Ab[(long)r * K + (kb + 1) * 8 + kc];
            bv = *(const float4*)&Bb[(long)r * K + (kb + 1) * 8 + kc];
        }
        const float* Ac = As[kb & 1];
        const float* Bc = Bs[kb & 1];
#pragma unroll
        for (int k = 0; k < 8; k++) {
            float4 a0 = *(const float4*)&Ac[k*132 + ty*4];
            float4 a1 = *(const float4*)&Ac[k*132 + 64 + ty*4];
            ulonglong2 b0 = *(const ulonglong2*)&Bc[k*132 + tx*4];
            ulonglong2 b1 = *(const ulonglong2*)&Bc[k*132 + 64 + tx*4];
            float a[8] = {a0.x,a0.y,a0.z,a0.w,a1.x,a1.y,a1.z,a1.w};
            unsigned long long bb[4] = {b0.x, b0.y, b1.x, b1.y};
#pragma unroll
            for (int i = 0; i < 8; i++) {
                unsigned long long ap = fpack(a[i], a[i]);
#pragma unroll
                for (int j = 0; j < 4; j++) ffma2(acc2[i][j], ap, bb[j]);
            }
        }
        if (kb + 1 < nb) {
            int nx = (kb + 1) & 1;
            As[nx][(kc+0)*132+r] = av.x; As[nx][(kc+1)*132+r] = av.y;
            As[nx][(kc+2)*132+r] = av.z; As[nx][(kc+3)*132+r] = av.w;
            Bs[nx][(kc+0)*132+r] = bv.x; Bs[nx][(kc+1)*132+r] = bv.y;
            Bs[nx][(kc+2)*132+r] = bv.z; Bs[nx][(kc+3)*132+r] = bv.w;
        }
        __syncthreads();
    }

    const float* bp = bias + z * sbz + blockIdx.y * 128;
    float4 bq0 = *(const float4*)&bp[tx*4];
    float4 bq1 = *(const float4*)&bp[64 + tx*4];
#pragma unroll
    for (int i = 0; i < 8; i++) {
        int m = blockIdx.x * 128 + ((i < 4) ? ty*4 + i : 64 + ty*4 + (i-4));
        long base = z * sCz + (long)m * N + blockIdx.y * 128;
        float4 o0, o1;
        o0.x = f2lo(acc2[i][0]) + bq0.x; o0.y = f2hi(acc2[i][0]) + bq0.y;
        o0.z = f2lo(acc2[i][1]) + bq0.z; o0.w = f2hi(acc2[i][1]) + bq0.w;
        o1.x = f2lo(acc2[i][2]) + bq1.x; o1.y = f2hi(acc2[i][2]) + bq1.y;
        o1.z = f2lo(acc2[i][3]) + bq1.z; o1.w = f2hi(acc2[i][3]) + bq1.w;
        *(float4*)&C[base + tx*4]      = o0;
        *(float4*)&C[base + 64 + tx*4] = o1;
    }
}

// ---------------- 2b. fused word attention + sum over words (FFMA2) --------
__global__ __launch_bounds__(256, 2) void k_uword(
    const float* __restrict__ waW, const float* __restrict__ wab)
{
    __shared__ float As[2][1056];
    __shared__ float Bs[2][1056];
    int t  = threadIdx.x;
    int s  = blockIdx.x;                 // sentence
    const float* Bb = waW + (long)blockIdx.y * 128 * HS_;
    int r  = t >> 1;                     // 0..127 (= word index for A)
    int kc = (t & 1) * 4;
    int tx = t & 15, ty = t >> 4;

    auto loadA = [&](int k0) -> float4 {
        int k   = k0 + kc;
        int dir = k >> 8;
        int hw  = k & 255;
        return *(const float4*)&g_H[((long)(dir * W_ + r) * S_ + s) * HW_ + hw];
    };

    float4 av = loadA(0);
    float4 bv = *(const float4*)&Bb[(long)r * HS_ + kc];
    As[0][(kc+0)*132+r] = av.x; As[0][(kc+1)*132+r] = av.y;
    As[0][(kc+2)*132+r] = av.z; As[0][(kc+3)*132+r] = av.w;
    Bs[0][(kc+0)*132+r] = bv.x; Bs[0][(kc+1)*132+r] = bv.y;
    Bs[0][(kc+2)*132+r] = bv.z; Bs[0][(kc+3)*132+r] = bv.w;
    __syncthreads();

    unsigned long long acc2[8][4];
#pragma unroll
    for (int i = 0; i < 8; i++)
#pragma unroll
        for (int j = 0; j < 4; j++) acc2[i][j] = 0ULL;

    const int nb = HS_ >> 3;   // 64
    for (int kb = 0; kb < nb; kb++) {
        if (kb + 1 < nb) {
            av = loadA((kb + 1) * 8);
            bv = *(const float4*)&Bb[(long)r * HS_ + (kb + 1) * 8 + kc];
        }
        const float* Ac = As[kb & 1];
        const float* Bc = Bs[kb & 1];
#pragma unroll
        for (int k = 0; k < 8; k++) {
            float4 a0 = *(const float4*)&Ac[k*132 + ty*4];
            float4 a1 = *(const float4*)&Ac[k*132 + 64 + ty*4];
            ulonglong2 b0 = *(const ulonglong2*)&Bc[k*132 + tx*4];
            ulonglong2 b1 = *(const ulonglong2*)&Bc[k*132 + 64 + tx*4];
            float a[8] = {a0.x,a0.y,a0.z,a0.w,a1.x,a1.y,a1.z,a1.w};
            unsigned long long bb[4] = {b0.x, b0.y, b1.x, b1.y};
#pragma unroll
            for (int i = 0; i < 8; i++) {
                unsigned long long ap = fpack(a[i], a[i]);
#pragma unroll
                for (int j = 0; j < 4; j++) ffma2(acc2[i][j], ap, bb[j]);
            }
        }
        if (kb + 1 < nb) {
            int nx = (kb + 1) & 1;
            As[nx][(kc+0)*132+r] = av.x; As[nx][(kc+1)*132+r] = av.y;
            As[nx][(kc+2)*132+r] = av.z; As[nx][(kc+3)*132+r] = av.w;
            Bs[nx][(kc+0)*132+r] = bv.x; Bs[nx][(kc+1)*132+r] = bv.y;
            Bs[nx][(kc+2)*132+r] = bv.z; Bs[nx][(kc+3)*132+r] = bv.w;
        }
        __syncthreads();
    }

    // epilogue: v = tanh(acc + bias); per-thread sum over its 8 rows,
    // then cross-ty reduction in SMEM -> g_ssum[s][n0 + col]
    const float* bp = wab + blockIdx.y * 128;
    float rsum[8];
#pragma unroll
    for (int j = 0; j < 8; j++) {
        int col = (j < 4) ? tx*4 + j : 64 + tx*4 + (j-4);
        float bj = bp[col];
        float sum = 0.f;
        int j2 = j >> 1;            // acc2 pair index: cols (even,odd)
        if ((j & 1) == 0) {
#pragma unroll
            for (int i = 0; i < 8; i++) sum += ftanh(f2lo(acc2[i][j2]) + bj);
        } else {
#pragma unroll
            for (int i = 0; i < 8; i++) sum += ftanh(f2hi(acc2[i][j2]) + bj);
        }
        rsum[j] = sum;
    }
    __syncthreads();
    float* red = &As[0][0];               // [16][132]
#pragma unroll
    for (int j = 0; j < 8; j++) {
        int col = (j < 4) ? tx*4 + j : 64 + tx*4 + (j-4);
        red[ty*132 + col] = rsum[j];
    }
    __syncthreads();
    if (t < 128) {
        float a = 0.f;
#pragma unroll
        for (int y = 0; y < 16; y++) a += red[y*132 + t];
        g_ssum[s * HS_ + blockIdx.y * 128 + t] = a;
    }
}

// ---------------- 2c. small generic GEMM (M=64 cases) ----------------------
#define BM 64
#define BN 64
#define BK 32
__global__ __launch_bounds__(256) void k_gemm(
    const float* __restrict__ A, const float* __restrict__ B,
    const float* __restrict__ bias, float* __restrict__ C,
    int M, int N, int K, int actTanh,
    long sAz, long sBz, long sbz, long sCz)
{
    __shared__ float As2[BK][BM + 1];
    __shared__ float Bs2[BK][BN + 1];
    int t  = threadIdx.x;
    int tx = t & 15, ty = t >> 4;
    int z  = blockIdx.z;
    const float* Ab = A + z * sAz + (long)blockIdx.x * BM * K;
    const float* Bb = B + z * sBz + (long)blockIdx.y * BN * K;
    float acc[4][4] = {};
    for (int k0 = 0; k0 < K; k0 += BK) {
#pragma unroll
        for (int j = 0; j < 8; j++) {
            int idx = j * 256 + t;
            int m = idx >> 5, k = idx & 31;
            As2[k][m] = Ab[(long)m * K + k0 + k];
            Bs2[k][m] = Bb[(long)m * K + k0 + k];
        }
        __syncthreads();
#pragma unroll 8
        for (int k = 0; k < BK; k++) {
            float a0 = As2[k][ty*4+0], a1 = As2[k][ty*4+1], a2 = As2[k][ty*4+2], a3 = As2[k][ty*4+3];
            float b0 = Bs2[k][tx*4+0], b1 = Bs2[k][tx*4+1], b2 = Bs2[k][tx*4+2], b3 = Bs2[k][tx*4+3];
            acc[0][0]=fmaf(a0,b0,acc[0][0]); acc[0][1]=fmaf(a0,b1,acc[0][1]);
            acc[0][2]=fmaf(a0,b2,acc[0][2]); acc[0][3]=fmaf(a0,b3,acc[0][3]);
            acc[1][0]=fmaf(a1,b0,acc[1][0]); acc[1][1]=fmaf(a1,b1,acc[1][1]);
            acc[1][2]=fmaf(a1,b2,acc[1][2]); acc[1][3]=fmaf(a1,b3,acc[1][3]);
            acc[2][0]=fmaf(a2,b0,acc[2][0]); acc[2][1]=fmaf(a2,b1,acc[2][1]);
            acc[2][2]=fmaf(a2,b2,acc[2][2]); acc[2][3]=fmaf(a2,b3,acc[2][3]);
            acc[3][0]=fmaf(a3,b0,acc[3][0]); acc[3][1]=fmaf(a3,b1,acc[3][1]);
            acc[3][2]=fmaf(a3,b2,acc[3][2]); acc[3][3]=fmaf(a3,b3,acc[3][3]);
        }
        __syncthreads();
    }
    const float* bp = bias + z * sbz;
#pragma unroll
    for (int i = 0; i < 4; i++) {
        int m = blockIdx.x * BM + ty * 4 + i;
#pragma unroll
        for (int j = 0; j < 4; j++) {
            int n = blockIdx.y * BN + tx * 4 + j;
            float v = acc[i][j] + bp[n];
            if (actTanh) v = ftanh(v);
            C[z * sCz + (long)m * N + n] = v;
        }
    }
}

// ---------------- 3. word GRU recurrence (cluster of 4, K-split, FFMA2) ----
#define PADK 260                  // weight row pitch: conflict-free LDS.128
#define HROW 288                  // h row pitch: 4 x 72 (64 data + 8 pad)
#define GRU_SMEM ((3*64*PADK + 2*4*HROW + 192) * 4)   // 209664 B

extern __shared__ float smem_gru[];

__global__ void __cluster_dims__(4, 1, 1) __launch_bounds__(256, 1)
k_wordgru(const float* __restrict__ wWh, const float* __restrict__ wbh)
{
    float* Wsh  = smem_gru;                 // [3*64][PADK]
    float* hbuf = Wsh + 3 * 64 * PADK;      // [2][4][HROW]
    float* bhs  = hbuf + 2 * 4 * HROW;      // [192]

    int rank = blockIdx.x & 3;
    int cid  = blockIdx.x >> 2;
    int d    = cid >> 4;
    int s0   = (cid & 15) * 4;
    int j0   = rank * 64;
    int tid  = threadIdx.x;

    const float4* w4g = (const float4*)wWh;
    for (int i = tid; i < 3 * 64 * 64; i += 256) {
        int g  = i >> 12;
        int r2 = i & 4095;
        int jr = r2 >> 6, k4 = r2 & 63;
        float4 v = w4g[((long)d * G3W_ + g * 256 + j0 + jr) * 64 + k4];
        *(float4*)&Wsh[(g * 64 + jr) * PADK + k4 * 4] = v;
    }
    for (int i = tid; i < 192; i += 256)
        bhs[i] = wbh[d * G3W_ + (i >> 6) * 256 + j0 + (i & 63)];
    for (int i = tid; i < 2 * 4 * HROW; i += 256) hbuf[i] = 0.f;
    __syncthreads();
    asm volatile("barrier.cluster.arrive.aligned;" ::: "memory");
    asm volatile("barrier.cluster.wait.aligned;"   ::: "memory");

    int lane = tid & 31;
    int warp = tid >> 5;            // 0..7
    int jl   = lane & 7;
    int kq   = lane >> 3;           // 0..3 K-quarter; also output sentence
    int jj   = warp * 8 + jl;       // 0..63
    int dim  = j0 + jj;
    int s    = s0 + kq;

    float bhr = bhs[jj], bhz = bhs[64 + jj], bhn = bhs[128 + jj];
    const ulonglong2* wR2 = (const ulonglong2*)&Wsh[(  0 + jj) * PADK] + kq * 16;
    const ulonglong2* wZ2 = (const ulonglong2*)&Wsh[( 64 + jj) * PADK] + kq * 16;
    const ulonglong2* wN2 = (const ulonglong2*)&Wsh[(128 + jj) * PADK] + kq * 16;

    // DSMEM push targets (per buffer parity): skewed h slot for (sent=kq, dim)
    unsigned rem[2][4];
#pragma unroll
    for (int b = 0; b < 2; b++) {
        unsigned la = su32(&hbuf[(b * 4 + kq) * HROW + dim + rank * 8]);
#pragma unroll
        for (int tcta = 0; tcta < 4; tcta++)
            asm volatile("mapa.shared::cluster.u32 %0, %1, %2;"
                         : "=r"(rem[b][tcta]) : "r"(la), "r"(tcta));
    }

    const long strideW = (long)S_ * G3W_;
    const float* gi = g_GI + ((long)(d * W_) * S_ + s) * G3W_ + dim;
    float* gh = g_H + ((long)(d * W_) * S_ + s) * HW_ + dim;

    float pR = __ldg(gi), pZ = __ldg(gi + 256), pN = __ldg(gi + 512);

    for (int w = 0; w < W_; w++) {
        int cur = w & 1, nxt = cur ^ 1;

        float giR = pR, giZ = pZ, giN = pN;
        const float* gnx = (w + 1 < W_) ? gi + strideW : gi;
        pR = __ldg(gnx); pZ = __ldg(gnx + 256); pN = __ldg(gnx + 512);

        const ulonglong2* h0 = (const ulonglong2*)&hbuf[(cur * 4 + 0) * HROW] + kq * 18;
        const ulonglong2* h1 = (const ulonglong2*)&hbuf[(cur * 4 + 1) * HROW] + kq * 18;
        const ulonglong2* h2 = (const ulonglong2*)&hbuf[(cur * 4 + 2) * HROW] + kq * 18;
        const ulonglong2* h3 = (const ulonglong2*)&hbuf[(cur * 4 + 3) * HROW] + kq * 18;

        unsigned long long AR0=0,AZ0=0,AN0=0, AR1=0,AZ1=0,AN1=0;
        unsigned long long AR2=0,AZ2=0,AN2=0, AR3=0,AZ3=0,AN3=0;
#pragma unroll
        for (int i = 0; i < 16; i++) {
            ulonglong2 wr = wR2[i], wz = wZ2[i], wn = wN2[i];
            ulonglong2 hv;
            hv = h0[i];
            ffma2(AR0, wr.x, hv.x); ffma2(AR0, wr.y, hv.y);
            ffma2(AZ0, wz.x, hv.x); ffma2(AZ0, wz.y, hv.y);
            ffma2(AN0, wn.x, hv.x); ffma2(AN0, wn.y, hv.y);
            hv = h1[i];
            ffma2(AR1, wr.x, hv.x); ffma2(AR1, wr.y, hv.y);
            ffma2(AZ1, wz.x, hv.x); ffma2(AZ1, wz.y, hv.y);
            ffma2(AN1, wn.x, hv.x); ffma2(AN1, wn.y, hv.y);
            hv = h2[i];
            ffma2(AR2, wr.x, hv.x); ffma2(AR2, wr.y, hv.y);
            ffma2(AZ2, wz.x, hv.x); ffma2(AZ2, wz.y, hv.y);
            ffma2(AN2, wn.x, hv.x); ffma2(AN2, wn.y, hv.y);
            hv = h3[i];
            ffma2(AR3, wr.x, hv.x); ffma2(AR3, wr.y, hv.y);
            ffma2(AZ3, wz.x, hv.x); ffma2(AZ3, wz.y, hv.y);
            ffma2(AN3, wn.x, hv.x); ffma2(AN3, wn.y, hv.y);
        }

        float aR0 = f2sum(AR0), aZ0 = f2sum(AZ0), aN0 = f2sum(AN0);
        float aR1 = f2sum(AR1), aZ1 = f2sum(AZ1), aN1 = f2sum(AN1);
        float aR2 = f2sum(AR2), aZ2 = f2sum(AZ2), aN2 = f2sum(AN2);
        float aR3 = f2sum(AR3), aZ3 = f2sum(AZ3), aN3 = f2sum(AN3);

        // reduce partial sums over kq (lanes ^8, ^16 share jj)
#pragma unroll
        for (int m = 8; m <= 16; m <<= 1) {
            aR0 += __shfl_xor_sync(0xffffffffu, aR0, m);
            aZ0 += __shfl_xor_sync(0xffffffffu, aZ0, m);
            aN0 += __shfl_xor_sync(0xffffffffu, aN0, m);
            aR1 += __shfl_xor_sync(0xffffffffu, aR1, m);
            aZ1 += __shfl_xor_sync(0xffffffffu, aZ1, m);
            aN1 += __shfl_xor_sync(0xffffffffu, aN1, m);
            aR2 += __shfl_xor_sync(0xffffffffu, aR2, m);
            aZ2 += __shfl_xor_sync(0xffffffffu, aZ2, m);
            aN2 += __shfl_xor_sync(0xffffffffu, aN2, m);
            aR3 += __shfl_xor_sync(0xffffffffu, aR3, m);
            aZ3 += __shfl_xor_sync(0xffffffffu, aZ3, m);
            aN3 += __shfl_xor_sync(0xffffffffu, aN3, m);
        }

        // thread kq finishes sentence kq
        float aR = (kq < 2) ? (kq == 0 ? aR0 : aR1) : (kq == 2 ? aR2 : aR3);
        float aZ = (kq < 2) ? (kq == 0 ? aZ0 : aZ1) : (kq == 2 ? aZ2 : aZ3);
        float aN = (kq < 2) ? (kq == 0 ? aN0 : aN1) : (kq == 2 ? aN2 : aN3);

        float hold = hbuf[(cur * 4 + kq) * HROW + dim + rank * 8];
        float r  = fsigm(giR + aR + bhr);
        float z  = fsigm(giZ + aZ + bhz);
        float n  = ftanh(giN + r * (aN + bhn));
        float hp = (1.f - z) * n + z * hold;

        // push h' to all 4 CTAs, release, overlap global store with barrier
#pragma unroll
        for (int tcta = 0; tcta < 4; tcta++)
            asm volatile("st.shared::cluster.f32 [%0], %1;"
                         :: "r"(rem[nxt][tcta]), "f"(hp) : "memory");
        asm volatile("barrier.cluster.arrive.aligned;" ::: "memory");  // release

        *gh = hp;
        gh += (long)S_ * HW_;
        gi += strideW;

        asm volatile("barrier.cluster.wait.aligned;"   ::: "memory");  // acquire
    }
}

// ---------------- 6. sentence encoder pointwise (h0 = 0) -------------------
__global__ void k_sentenc(const float* __restrict__ sbh) {
    int idx = blockIdx.x * blockDim.x + threadIdx.x;  // 65536
    int d = idx >> 15;
    int s = (idx >> 9) & 63;
    int h = idx & 511;
    const float* gi = &g_GIS[(d * S_ + s) * G3S_];
    float r  = fsigm(gi[h]       + sbh[d * G3S_ + h]);
    float zz = fsigm(gi[512 + h] + sbh[d * G3S_ + 512 + h]);
    float n  = ftanh(gi[1024 + h] + r * sbh[d * G3S_ + 1024 + h]);
    g_SE[s * 1024 + d * 512 + h] = (1.f - zz) * n;
}

// ---------------- 7. outputs -----------------------------------------------
__global__ void k_ones(float* out, int n) {
    int i = blockIdx.x * 256 + threadIdx.x;
    if (i < n) out[i] = 1.0f;
}

__global__ void k_final(const float* __restrict__ doW, const float* __restrict__ dob,
                        float* __restrict__ out, int out_size) {
    __shared__ float doc[1024];
    __shared__ float red[256];
    __shared__ float logit[16];
    int t = threadIdx.x;
    for (int n = t; n < 1024; n += 256) {
        float a = 0.f;
        for (int s = 0; s < S_; s++) a += g_US[s * 1024 + n];
        doc[n] = a;
    }
    __syncthreads();
    for (int c = 0; c < C_; c++) {
        float p = 0.f;
        for (int n = t; n < 1024; n += 256) p = fmaf(doc[n], doW[c * 1024 + n], p);
        red[t] = p; __syncthreads();
        for (int st = 128; st > 0; st >>= 1) {
            if (t < st) red[t] += red[t + st];
            __syncthreads();
        }
        if (t == 0) logit[c] = red[0] + dob[c];
        __syncthreads();
    }
    if (t == 0) {
        float m = -1e30f;
        for (int c = 0; c < C_; c++) m = fmaxf(m, logit[c]);
        float se = 0.f;
        for (int c = 0; c < C_; c++) se += expf(logit[c] - m);   // keep accurate
        float lse = m + logf(se);
        for (int c = 0; c < C_; c++) out[out_size - C_ + c] = logit[c] - lse;
    }
}

// ---------------- launcher -------------------------------------------------
extern "C" void kernel_launch(void* const* d_in, const int* in_sizes, int n_in,
                              void* d_out, int out_size) {
    const int*   doc = (const int*)  d_in[0];
    const float* emb = (const float*)d_in[1];
    const float* wWi = (const float*)d_in[2];
    const float* wWh = (const float*)d_in[3];
    const float* wbi = (const float*)d_in[4];
    const float* wbh = (const float*)d_in[5];
    const float* sWi = (const float*)d_in[6];
    const float* sbi = (const float*)d_in[8];
    const float* sbh = (const float*)d_in[9];
    const float* waW = (const float*)d_in[10];
    const float* wab = (const float*)d_in[11];
    const float* saW = (const float*)d_in[13];
    const float* sab = (const float*)d_in[14];
    const float* doW = (const float*)d_in[16];
    const float* dob = (const float*)d_in[17];
    float* out = (float*)d_out;

    cudaFuncSetAttribute(k_wordgru, cudaFuncAttributeMaxDynamicSharedMemorySize, GRU_SMEM);

    float *pX, *pGI, *pS, *pGIS, *pSE, *pUS;
    cudaGetSymbolAddress((void**)&pX,  g_X);
    cudaGetSymbolAddress((void**)&pGI, g_GI);
    cudaGetSymbolAddress((void**)&pS,  g_ssum);
    cudaGetSymbolAddress((void**)&pGIS,g_GIS);
    cudaGetSymbolAddress((void**)&pSE, g_SE);
    cudaGetSymbolAddress((void**)&pUS, g_US);

    // 1. gather embeddings
    k_gather<<<2048, 256>>>(doc, emb);

    // 2. GI[d] = X @ wWi[d].T + wbi[d]   (M=8192, N=768, K=256)
    k_gemm128<<<dim3(64, 6, 2), 256>>>(pX, wWi, wbi, pGI, 8192, 768, 256,
                                       0, 768L * 256, 768, 8192L * 768);

    // 3. recurrence -> g_H  (K-split, FFMA2)
    k_wordgru<<<128, 256, GRU_SMEM>>>(wWh, wbh);

    // 4+5+6 fused: g_ssum[s] = sum_w tanh(wordenc[s,w] @ waW.T + wab)
    k_uword<<<dim3(64, 4), 256>>>(waW, wab);

    // 7. GIS[d] = sent_summ @ sWi[d].T + sbi[d]  (M=64, N=1536, K=512)
    k_gemm<<<dim3(1, 24, 2), 256>>>(pS, sWi, sbi, pGIS, 64, 1536, 512, 0,
                                    0, 1536L * 512, 1536, 64L * 1536);

    // 8. sentenc pointwise
    k_sentenc<<<256, 256>>>(sbh);

    // 9. u_sent = tanh(sentenc @ saW.T + sab)   (M=64, N=1024, K=1024)
    k_gemm<<<dim3(1, 16, 1), 256>>>(pSE, saW, sab, pUS, 64, 1024, 1024, 1, 0, 0, 0, 0);

    // 10. outputs
    int nOnes = out_size - C_;
    k_ones<<<(nOnes + 255) / 256, 256>>>(out, nOnes);
    k_final<<<1, 256>>>(doW, dob, out, out_size);
}